// round 3
// baseline (speedup 1.0000x reference)
#include <cuda_runtime.h>
#include <math.h>

#define BB   2
#define SEQ  2048
#define HK   16
#define HV   32
#define DK   128
#define DV   128
#define QKV  8192
#define NTOK (BB*SEQ)
#define EPSF 1e-6f
#define TT   8   // tokens per conv block

typedef unsigned long long ull;

// ---------------- packed f32x2 helpers (Blackwell) ----------------
__device__ __forceinline__ ull fma2(ull a, ull b, ull c) {
    ull d; asm("fma.rn.f32x2 %0, %1, %2, %3;" : "=l"(d) : "l"(a), "l"(b), "l"(c)); return d;
}
__device__ __forceinline__ ull mul2(ull a, ull b) {
    ull d; asm("mul.rn.f32x2 %0, %1, %2;" : "=l"(d) : "l"(a), "l"(b)); return d;
}
__device__ __forceinline__ ull add2(ull a, ull b) {
    ull d; asm("add.rn.f32x2 %0, %1, %2;" : "=l"(d) : "l"(a), "l"(b)); return d;
}
__device__ __forceinline__ ull pack2(float lo, float hi) {
    ull d; asm("mov.b64 %0, {%1, %2};" : "=l"(d)
               : "r"(__float_as_uint(lo)), "r"(__float_as_uint(hi))); return d;
}
__device__ __forceinline__ float hadd2(ull a) {
    unsigned lo, hi; asm("mov.b64 {%0, %1}, %2;" : "=r"(lo), "=r"(hi) : "l"(a));
    return __uint_as_float(lo) + __uint_as_float(hi);
}

// ---------------- scratch (device globals: allocation-free) ----------------
__device__ float  g_q[NTOK * HK * DK];
__device__ float  g_k[NTOK * HK * DK];
__device__ float  g_v[NTOK * HV * DV];
__device__ float2 g_gb[NTOK * HV];       // (exp(g), beta)

// ---------------- kernel 1: causal conv + SiLU + l2norm, 8 tokens/block -----
// grid: (NTOK/TT, 64)  block: 128
__global__ __launch_bounds__(128) void conv_kernel(
    const float* __restrict__ x, const float* __restrict__ w)
{
    const int tile = blockIdx.x;
    const int slot = blockIdx.y;
    const int tid  = threadIdx.x;
    const int ch   = slot * 128 + tid;
    const int t0   = tile * TT;            // global token index (tile never crosses seq)
    const int s0   = t0 & (SEQ - 1);       // position within sequence

    const float4 wv = reinterpret_cast<const float4*>(w)[ch];  // w[ch,0..3]

    float xv[TT + 3];
    #pragma unroll
    for (int j = 0; j < TT + 3; j++) {
        const int off = j - 3;
        xv[j] = (s0 + off >= 0) ? x[(size_t)(t0 + off) * QKV + ch] : 0.0f;
    }

    float y[TT];
    #pragma unroll
    for (int j = 0; j < TT; j++) {
        // y[s] = w0*x[s-3] + w1*x[s-2] + w2*x[s-1] + w3*x[s]
        float acc = wv.x * xv[j] + wv.y * xv[j + 1] + wv.z * xv[j + 2] + wv.w * xv[j + 3];
        y[j] = acc / (1.0f + __expf(-acc));   // SiLU
    }

    if (slot < 32) {
        float ss[TT];
        #pragma unroll
        for (int j = 0; j < TT; j++) ss[j] = y[j] * y[j];
        #pragma unroll
        for (int o = 16; o; o >>= 1) {
            #pragma unroll
            for (int j = 0; j < TT; j++) ss[j] += __shfl_xor_sync(0xffffffffu, ss[j], o);
        }
        __shared__ float red[4][TT];
        if ((tid & 31) == 0) {
            #pragma unroll
            for (int j = 0; j < TT; j++) red[tid >> 5][j] = ss[j];
        }
        __syncthreads();
        #pragma unroll
        for (int j = 0; j < TT; j++) {
            float tot = red[0][j] + red[1][j] + red[2][j] + red[3][j];
            y[j] *= rsqrtf(tot + EPSF);
        }
        if (slot < 16) {
            #pragma unroll
            for (int j = 0; j < TT; j++)
                g_q[(size_t)(t0 + j) * HK * DK + slot * DK + tid] = y[j];
        } else {
            #pragma unroll
            for (int j = 0; j < TT; j++)
                g_k[(size_t)(t0 + j) * HK * DK + (slot - 16) * DK + tid] = y[j];
        }
    } else {
        #pragma unroll
        for (int j = 0; j < TT; j++)
            g_v[(size_t)(t0 + j) * HV * DV + (slot - 32) * DV + tid] = y[j];
    }
}

// ---------------- kernel 2: gating precompute --------------------------------
__global__ void gate_kernel(const float* __restrict__ b_in,
                            const float* __restrict__ a_in,
                            const float* __restrict__ dt_bias,
                            const float* __restrict__ alog)
{
    int i = blockIdx.x * blockDim.x + threadIdx.x;
    if (i >= NTOK * HV) return;
    int h = i & (HV - 1);
    float xx = a_in[i] + dt_bias[h];
    float sp = fmaxf(xx, 0.0f) + log1pf(expf(-fabsf(xx)));
    float g  = -expf(alog[h]) * sp;
    float eg = expf(g);
    float bb = b_in[i];
    float beta = 1.0f / (1.0f + expf(-bb));
    g_gb[i] = make_float2(eg, beta);
}

// ---------------- kernel 3: sequential gated delta-rule scan (f32x2) ---------
// grid: 64 (= B*HV), block: 128. Thread tid owns state column S[:, tid],
// held as 64 packed f32x2 registers (rows 2i, 2i+1).
__global__ __launch_bounds__(128, 1) void scan_kernel(float* __restrict__ out)
{
    const int bh  = blockIdx.x;
    const int bb  = bh / HV;
    const int h   = bh % HV;
    const int hk  = h >> 1;               // GQA: q/k head = h / (HV/HK)
    const int tid = threadIdx.x;
    const float scale = 0.08838834764831845f;  // 128^-0.5

    __shared__ __align__(16) float ksh[2][DK];
    __shared__ __align__(16) float qsh[2][DK];

    ull S2[64];
    #pragma unroll
    for (int i = 0; i < 64; i++) S2[i] = 0ull;

    const size_t row0 = (size_t)bb * SEQ;

    // prefetch t = 0
    float kv = g_k[row0 * HK * DK + hk * DK + tid];
    float qv = g_q[row0 * HK * DK + hk * DK + tid];
    float vv = g_v[row0 * HV * DV + h  * DV + tid];
    float2 gb = g_gb[row0 * HV + h];

    for (int t = 0; t < SEQ; t++) {
        const int pb = t & 1;
        ksh[pb][tid] = kv;
        qsh[pb][tid] = qv;
        const float  vcur = vv;
        const float2 gcur = gb;
        __syncthreads();

        // prefetch t+1 (lands while we compute)
        if (t + 1 < SEQ) {
            const size_t r2 = row0 + t + 1;
            kv = g_k[r2 * HK * DK + hk * DK + tid];
            qv = g_q[r2 * HK * DK + hk * DK + tid];
            vv = g_v[r2 * HV * DV + h  * DV + tid];
            gb = g_gb[r2 * HV + h];
        }

        const ulonglong2* k2 = reinterpret_cast<const ulonglong2*>(ksh[pb]);
        const ulonglong2* q2 = reinterpret_cast<const ulonglong2*>(qsh[pb]);

        // loop A (read-only): pred0 = k^T S_old   (pred = eg * pred0)
        ull pa0 = 0ull, pa1 = 0ull, pa2 = 0ull, pa3 = 0ull;
        #pragma unroll
        for (int j = 0; j < 32; j += 2) {
            const ulonglong2 ka = k2[j];
            const ulonglong2 kb = k2[j + 1];
            pa0 = fma2(ka.x, S2[2*j    ], pa0);
            pa1 = fma2(ka.y, S2[2*j + 1], pa1);
            pa2 = fma2(kb.x, S2[2*j + 2], pa2);
            pa3 = fma2(kb.y, S2[2*j + 3], pa3);
        }
        const float pred0 = hadd2(add2(add2(pa0, pa1), add2(pa2, pa3)));

        const float eg = gcur.x, beta = gcur.y;
        const float u  = beta * (vcur - eg * pred0);
        const ull u2   = pack2(u, u);
        const ull eg2  = pack2(eg, eg);

        // loop B: S = eg*S + k*u  (fused), o = q^T S_new
        ull oa0 = 0ull, oa1 = 0ull, oa2 = 0ull, oa3 = 0ull;
        #pragma unroll
        for (int j = 0; j < 32; j += 2) {
            const ulonglong2 ka = k2[j];
            const ulonglong2 kb = k2[j + 1];
            const ulonglong2 qa = q2[j];
            const ulonglong2 qb = q2[j + 1];
            S2[2*j    ] = fma2(S2[2*j    ], eg2, mul2(ka.x, u2));
            S2[2*j + 1] = fma2(S2[2*j + 1], eg2, mul2(ka.y, u2));
            S2[2*j + 2] = fma2(S2[2*j + 2], eg2, mul2(kb.x, u2));
            S2[2*j + 3] = fma2(S2[2*j + 3], eg2, mul2(kb.y, u2));
            oa0 = fma2(qa.x, S2[2*j    ], oa0);
            oa1 = fma2(qa.y, S2[2*j + 1], oa1);
            oa2 = fma2(qb.x, S2[2*j + 2], oa2);
            oa3 = fma2(qb.y, S2[2*j + 3], oa3);
        }
        const float o = hadd2(add2(add2(oa0, oa1), add2(oa2, oa3))) * scale;

        out[((row0 + t) * HV + h) * DV + tid] = o;
    }
}

// ---------------- launch ------------------------------------------------------
extern "C" void kernel_launch(void* const* d_in, const int* in_sizes, int n_in,
                              void* d_out, int out_size)
{
    const float* x    = (const float*)d_in[0];  // mixed_qkv [4096, 8192]
    const float* b    = (const float*)d_in[1];  // [4096, 32]
    const float* a    = (const float*)d_in[2];  // [4096, 32]
    const float* w    = (const float*)d_in[3];  // conv_weights [8192, 4]
    const float* dt   = (const float*)d_in[4];  // [32]
    const float* alog = (const float*)d_in[5];  // [32]
    // d_in[6] = cu_seqlens (equal-length; unused)

    conv_kernel<<<dim3(NTOK / TT, 64), 128>>>(x, w);
    gate_kernel<<<(NTOK * HV + 255) / 256, 256>>>(b, a, dt, alog);
    scan_kernel<<<64, 128>>>((float*)d_out);
}

// round 5
// speedup vs baseline: 1.8015x; 1.8015x over previous
#include <cuda_runtime.h>
#include <math.h>

#define BB   2
#define SEQ  2048
#define HK   16
#define HV   32
#define DK   128
#define DV   128
#define QKV  8192
#define NTOK (BB*SEQ)
#define EPSF 1e-6f
#define TT   8   // tokens per conv block

// ---------------- scratch (device globals: allocation-free) ----------------
__device__ float  g_q[NTOK * HK * DK];
__device__ float  g_k[NTOK * HK * DK];
__device__ float  g_v[NTOK * HV * DV];
__device__ float2 g_gb[NTOK * HV];       // (exp(g), beta)

// ---------------- kernel 1: causal conv + SiLU + l2norm, 8 tokens/block -----
// grid: (NTOK/TT, 64)  block: 128
__global__ __launch_bounds__(128) void conv_kernel(
    const float* __restrict__ x, const float* __restrict__ w)
{
    const int tile = blockIdx.x;
    const int slot = blockIdx.y;
    const int tid  = threadIdx.x;
    const int ch   = slot * 128 + tid;
    const int t0   = tile * TT;            // tile never crosses a sequence boundary
    const int s0   = t0 & (SEQ - 1);

    const float4 wv = reinterpret_cast<const float4*>(w)[ch];  // w[ch,0..3]

    float xv[TT + 3];
    #pragma unroll
    for (int j = 0; j < TT + 3; j++) {
        const int off = j - 3;
        xv[j] = (s0 + off >= 0) ? x[(size_t)(t0 + off) * QKV + ch] : 0.0f;
    }

    float y[TT];
    #pragma unroll
    for (int j = 0; j < TT; j++) {
        float acc = wv.x * xv[j] + wv.y * xv[j + 1] + wv.z * xv[j + 2] + wv.w * xv[j + 3];
        y[j] = acc / (1.0f + __expf(-acc));   // SiLU
    }

    if (slot < 32) {
        float ss[TT];
        #pragma unroll
        for (int j = 0; j < TT; j++) ss[j] = y[j] * y[j];
        #pragma unroll
        for (int o = 16; o; o >>= 1) {
            #pragma unroll
            for (int j = 0; j < TT; j++) ss[j] += __shfl_xor_sync(0xffffffffu, ss[j], o);
        }
        __shared__ float red[4][TT];
        if ((tid & 31) == 0) {
            #pragma unroll
            for (int j = 0; j < TT; j++) red[tid >> 5][j] = ss[j];
        }
        __syncthreads();
        #pragma unroll
        for (int j = 0; j < TT; j++) {
            float tot = red[0][j] + red[1][j] + red[2][j] + red[3][j];
            y[j] *= rsqrtf(tot + EPSF);
        }
        if (slot < 16) {
            #pragma unroll
            for (int j = 0; j < TT; j++)
                g_q[(size_t)(t0 + j) * HK * DK + slot * DK + tid] = y[j];
        } else {
            #pragma unroll
            for (int j = 0; j < TT; j++)
                g_k[(size_t)(t0 + j) * HK * DK + (slot - 16) * DK + tid] = y[j];
        }
    } else {
        #pragma unroll
        for (int j = 0; j < TT; j++)
            g_v[(size_t)(t0 + j) * HV * DV + (slot - 32) * DV + tid] = y[j];
    }
}

// ---------------- kernel 2: gating precompute --------------------------------
__global__ void gate_kernel(const float* __restrict__ b_in,
                            const float* __restrict__ a_in,
                            const float* __restrict__ dt_bias,
                            const float* __restrict__ alog)
{
    int i = blockIdx.x * blockDim.x + threadIdx.x;
    if (i >= NTOK * HV) return;
    int h = i & (HV - 1);
    float xx = a_in[i] + dt_bias[h];
    float sp = fmaxf(xx, 0.0f) + log1pf(expf(-fabsf(xx)));
    float g  = -expf(alog[h]) * sp;
    float eg = expf(g);
    float bb = b_in[i];
    float beta = 1.0f / (1.0f + expf(-bb));
    g_gb[i] = make_float2(eg, beta);
}

// ---------------- kernel 3: sequential gated delta-rule scan -----------------
// grid: 128 (= B*HV * 2 column-halves), block: 128.
// Thread pair (2c, 2c+1) owns state column `col`; thread rpart owns rows
// [rpart*64, rpart*64+64). State kept UNNORMALIZED: S_true = P * S_hat with
// P = running product of exp(g); re-folded when P < 1e-8 (g<=0 so P only
// shrinks). This removes the per-element decay multiply from the hot loop.
__global__ __launch_bounds__(128, 1) void scan_kernel(float* __restrict__ out)
{
    const int blk   = blockIdx.x;         // 0..127
    const int bh    = blk >> 1;
    const int half  = blk & 1;
    const int bb    = bh / HV;
    const int h     = bh % HV;
    const int hk    = h >> 1;             // GQA: q/k head = h / (HV/HK)
    const int tid   = threadIdx.x;
    const int col   = half * 64 + (tid >> 1);
    const int rpart = tid & 1;
    const int rbase = rpart * 64;
    const float scale = 0.08838834764831845f;  // 128^-0.5

    __shared__ __align__(16) float ksh[2][DK];
    __shared__ __align__(16) float qsh[2][DK];

    float S[64];                           // S_hat[rbase + i][col]
    #pragma unroll
    for (int i = 0; i < 64; i++) S[i] = 0.0f;
    float P = 1.0f, Pinv = 1.0f;

    const size_t row0 = (size_t)bb * SEQ;

    // prefetch t = 0
    float kv = g_k[row0 * HK * DK + hk * DK + tid];
    float qv = g_q[row0 * HK * DK + hk * DK + tid];
    float vv = g_v[row0 * HV * DV + h  * DV + col];
    float2 gb = g_gb[row0 * HV + h];
    float egInv = __fdividef(1.0f, gb.x);

    for (int t = 0; t < SEQ; t++) {
        const int pb = t & 1;
        ksh[pb][tid] = kv;
        qsh[pb][tid] = qv;
        const float vcur = vv;
        const float eg   = gb.x;
        const float beta = gb.y;
        const float egI  = egInv;
        __syncthreads();

        // prefetch t+1 (lands while we compute; reciprocal off critical path)
        if (t + 1 < SEQ) {
            const size_t r2 = row0 + t + 1;
            kv = g_k[r2 * HK * DK + hk * DK + tid];
            qv = g_q[r2 * HK * DK + hk * DK + tid];
            vv = g_v[r2 * HV * DV + h  * DV + col];
            gb = g_gb[r2 * HV + h];
            egInv = __fdividef(1.0f, gb.x);
        }

        const float4* k4 = reinterpret_cast<const float4*>(&ksh[pb][rbase]);
        const float4* q4 = reinterpret_cast<const float4*>(&qsh[pb][rbase]);

        // loop A: partial pred_hat = k[rows]^T S_hat
        float p0 = 0.f, p1 = 0.f, p2 = 0.f, p3 = 0.f;
        #pragma unroll
        for (int i = 0; i < 16; i++) {
            const float4 kk = k4[i];
            p0 += kk.x * S[4*i+0];
            p1 += kk.y * S[4*i+1];
            p2 += kk.z * S[4*i+2];
            p3 += kk.w * S[4*i+3];
        }
        float pp = (p0 + p1) + (p2 + p3);
        pp += __shfl_xor_sync(0xffffffffu, pp, 1);   // combine row halves

        // pred (decayed true state) = eg * P * pred_hat
        const float Pn    = P * eg;
        const float PinvN = Pinv * egI;
        const float u     = beta * (vcur - eg * P * pp);
        const float uP    = u * PinvN;

        // loop B: S_hat += k * uP ; o_part = q[rows]^T S_hat
        float o0 = 0.f, o1 = 0.f, o2 = 0.f, o3 = 0.f;
        #pragma unroll
        for (int i = 0; i < 16; i++) {
            const float4 kk = k4[i];
            const float4 qq = q4[i];
            S[4*i+0] += kk.x * uP;
            S[4*i+1] += kk.y * uP;
            S[4*i+2] += kk.z * uP;
            S[4*i+3] += kk.w * uP;
            o0 += qq.x * S[4*i+0];
            o1 += qq.y * S[4*i+1];
            o2 += qq.z * S[4*i+2];
            o3 += qq.w * S[4*i+3];
        }
        float oo = (o0 + o1) + (o2 + o3);
        oo += __shfl_xor_sync(0xffffffffu, oo, 1);

        if (rpart == 0)
            out[((row0 + t) * HV + h) * DV + col] = oo * (Pn * scale);

        // re-fold when P gets small (block-uniform branch; P is bitwise
        // identical across threads). Resets reciprocal drift too.
        if (Pn < 1e-8f) {
            #pragma unroll
            for (int i = 0; i < 64; i++) S[i] *= Pn;
            P = 1.0f; Pinv = 1.0f;
        } else {
            P = Pn; Pinv = PinvN;
        }
    }
}

// ---------------- launch ------------------------------------------------------
extern "C" void kernel_launch(void* const* d_in, const int* in_sizes, int n_in,
                              void* d_out, int out_size)
{
    const float* x    = (const float*)d_in[0];  // mixed_qkv [4096, 8192]
    const float* b    = (const float*)d_in[1];  // [4096, 32]
    const float* a    = (const float*)d_in[2];  // [4096, 32]
    const float* w    = (const float*)d_in[3];  // conv_weights [8192, 4]
    const float* dt   = (const float*)d_in[4];  // [32]
    const float* alog = (const float*)d_in[5];  // [32]
    // d_in[6] = cu_seqlens (equal-length; unused)

    conv_kernel<<<dim3(NTOK / TT, 64), 128>>>(x, w);
    gate_kernel<<<(NTOK * HV + 255) / 256, 256>>>(b, a, dt, alog);
    scan_kernel<<<128, 128>>>((float*)d_out);
}

// round 6
// speedup vs baseline: 2.7455x; 1.5240x over previous
#include <cuda_runtime.h>
#include <math.h>

#define BB   2
#define SEQ  2048
#define HK   16
#define HV   32
#define DK   128
#define DV   128
#define QKV  8192
#define NTOK (BB*SEQ)
#define EPSF 1e-6f
#define TT   8   // tokens per conv block
#define NW   (NTOK/4)   // 4-token windows

// ---------------- scratch (device globals: allocation-free) ----------------
__device__ float  g_q[NTOK * HK * DK];
__device__ float  g_k[NTOK * HK * DK];
__device__ float  g_v[NTOK * HV * DV];
__device__ float2 g_gb[NTOK * HV];            // (exp(g), beta)
__device__ float  g_dt[NW * HK * 16];         // per-window pairwise dot table

// ---------------- kernel 1: causal conv + SiLU + l2norm, 8 tokens/block -----
__global__ __launch_bounds__(128) void conv_kernel(
    const float* __restrict__ x, const float* __restrict__ w)
{
    const int tile = blockIdx.x;
    const int slot = blockIdx.y;
    const int tid  = threadIdx.x;
    const int ch   = slot * 128 + tid;
    const int t0   = tile * TT;
    const int s0   = t0 & (SEQ - 1);

    const float4 wv = reinterpret_cast<const float4*>(w)[ch];

    float xv[TT + 3];
    #pragma unroll
    for (int j = 0; j < TT + 3; j++) {
        const int off = j - 3;
        xv[j] = (s0 + off >= 0) ? x[(size_t)(t0 + off) * QKV + ch] : 0.0f;
    }

    float y[TT];
    #pragma unroll
    for (int j = 0; j < TT; j++) {
        float acc = wv.x * xv[j] + wv.y * xv[j + 1] + wv.z * xv[j + 2] + wv.w * xv[j + 3];
        y[j] = acc / (1.0f + __expf(-acc));   // SiLU
    }

    if (slot < 32) {
        float ss[TT];
        #pragma unroll
        for (int j = 0; j < TT; j++) ss[j] = y[j] * y[j];
        #pragma unroll
        for (int o = 16; o; o >>= 1) {
            #pragma unroll
            for (int j = 0; j < TT; j++) ss[j] += __shfl_xor_sync(0xffffffffu, ss[j], o);
        }
        __shared__ float red[4][TT];
        if ((tid & 31) == 0) {
            #pragma unroll
            for (int j = 0; j < TT; j++) red[tid >> 5][j] = ss[j];
        }
        __syncthreads();
        #pragma unroll
        for (int j = 0; j < TT; j++) {
            float tot = red[0][j] + red[1][j] + red[2][j] + red[3][j];
            y[j] *= rsqrtf(tot + EPSF);
        }
        if (slot < 16) {
            #pragma unroll
            for (int j = 0; j < TT; j++)
                g_q[(size_t)(t0 + j) * HK * DK + slot * DK + tid] = y[j];
        } else {
            #pragma unroll
            for (int j = 0; j < TT; j++)
                g_k[(size_t)(t0 + j) * HK * DK + (slot - 16) * DK + tid] = y[j];
        }
    } else {
        #pragma unroll
        for (int j = 0; j < TT; j++)
            g_v[(size_t)(t0 + j) * HV * DV + (slot - 32) * DV + tid] = y[j];
    }
}

// ---------------- kernel 2: gating precompute --------------------------------
__global__ void gate_kernel(const float* __restrict__ b_in,
                            const float* __restrict__ a_in,
                            const float* __restrict__ dt_bias,
                            const float* __restrict__ alog)
{
    int i = blockIdx.x * blockDim.x + threadIdx.x;
    if (i >= NTOK * HV) return;
    int h = i & (HV - 1);
    float xx = a_in[i] + dt_bias[h];
    float sp = fmaxf(xx, 0.0f) + log1pf(expf(-fabsf(xx)));
    float g  = -expf(alog[h]) * sp;
    float eg = expf(g);
    float bb = b_in[i];
    float beta = 1.0f / (1.0f + expf(-bb));
    g_gb[i] = make_float2(eg, beta);
}

// ---------------- kernel 2.5: per-window pairwise dot table ------------------
// For window tokens 1..4: Kk[i][j]=k_i.k_j (j<i), Kq[i][j]=q_i.k_j (j<=i).
// Layout (16 floats): [Kk21,Kk31,Kk32,Kk41, Kk42,Kk43,Kq11,Kq21,
//                      Kq22,Kq31,Kq32,Kq33,  Kq41,Kq42,Kq43,Kq44]
// grid (NW/4, HK), block 128 (4 warps, 1 window each)
__device__ __forceinline__ float dot4(float4 a, float4 b) {
    return a.x*b.x + a.y*b.y + a.z*b.z + a.w*b.w;
}
__global__ __launch_bounds__(128) void dot_kernel()
{
    const int warp = threadIdx.x >> 5;
    const int lane = threadIdx.x & 31;
    const int w    = blockIdx.x * 4 + warp;
    const int hk   = blockIdx.y;

    const size_t base = (size_t)(w * 4) * (HK * DK) + hk * DK + lane * 4;
    float4 k[4], q[4];
    #pragma unroll
    for (int i = 0; i < 4; i++) {
        k[i] = *reinterpret_cast<const float4*>(&g_k[base + (size_t)i * (HK * DK)]);
        q[i] = *reinterpret_cast<const float4*>(&g_q[base + (size_t)i * (HK * DK)]);
    }
    float s0  = dot4(k[1], k[0]), s1  = dot4(k[2], k[0]), s2  = dot4(k[2], k[1]);
    float s3  = dot4(k[3], k[0]), s4  = dot4(k[3], k[1]), s5  = dot4(k[3], k[2]);
    float s6  = dot4(q[0], k[0]), s7  = dot4(q[1], k[0]), s8  = dot4(q[1], k[1]);
    float s9  = dot4(q[2], k[0]), s10 = dot4(q[2], k[1]), s11 = dot4(q[2], k[2]);
    float s12 = dot4(q[3], k[0]), s13 = dot4(q[3], k[1]), s14 = dot4(q[3], k[2]);
    float s15 = dot4(q[3], k[3]);
    #pragma unroll
    for (int o = 16; o; o >>= 1) {
        s0  += __shfl_xor_sync(~0u, s0,  o); s1  += __shfl_xor_sync(~0u, s1,  o);
        s2  += __shfl_xor_sync(~0u, s2,  o); s3  += __shfl_xor_sync(~0u, s3,  o);
        s4  += __shfl_xor_sync(~0u, s4,  o); s5  += __shfl_xor_sync(~0u, s5,  o);
        s6  += __shfl_xor_sync(~0u, s6,  o); s7  += __shfl_xor_sync(~0u, s7,  o);
        s8  += __shfl_xor_sync(~0u, s8,  o); s9  += __shfl_xor_sync(~0u, s9,  o);
        s10 += __shfl_xor_sync(~0u, s10, o); s11 += __shfl_xor_sync(~0u, s11, o);
        s12 += __shfl_xor_sync(~0u, s12, o); s13 += __shfl_xor_sync(~0u, s13, o);
        s14 += __shfl_xor_sync(~0u, s14, o); s15 += __shfl_xor_sync(~0u, s15, o);
    }
    if (lane == 0) {
        float4* p = reinterpret_cast<float4*>(&g_dt[(size_t)(w * HK + hk) * 16]);
        p[0] = make_float4(s0,  s1,  s2,  s3);
        p[1] = make_float4(s4,  s5,  s6,  s7);
        p[2] = make_float4(s8,  s9,  s10, s11);
        p[3] = make_float4(s12, s13, s14, s15);
    }
}

// ---------------- kernel 3: windowed gated delta-rule scan --------------------
// grid: 128 (= B*HV * 2 column-halves), block: 256 (8 warps).
// Thread quartet (4c..4c+3) owns column col; lane rp owns rows [rp*32, rp*32+32).
// Processes 4 tokens per iteration: 8 independent dots vs S0, scalar window
// recurrence using the precomputed dot table, then one fused rank-4 update.
__global__ __launch_bounds__(256, 1) void scan_kernel(float* __restrict__ out)
{
    const int blk  = blockIdx.x;
    const int bh   = blk >> 1;
    const int half = blk & 1;
    const int bb   = bh / HV;
    const int h    = bh % HV;
    const int hk   = h >> 1;              // GQA
    const int tid  = threadIdx.x;
    const int col  = half * 64 + (tid >> 2);
    const int rp   = tid & 3;
    const float scale = 0.08838834764831845f;   // 128^-0.5

    // token rows stored as 4 chunks of 36 floats (32 data + 4 pad) to kill
    // bank conflicts between the 4 row-partitions; token stride 144 floats.
    __shared__ __align__(16) float ksh[2][4 * 144];
    __shared__ __align__(16) float qsh[2][4 * 144];

    float S[32];
    #pragma unroll
    for (int i = 0; i < 32; i++) S[i] = 0.0f;

    const size_t row0 = (size_t)bb * SEQ;
    const int ptok  = tid >> 6;           // which token of the window I stage
    const int ppos  = (tid * 2) & 127;    // which float pair
    const int psmem = ptok * 144 + (ppos >> 5) * 36 + (ppos & 31);

    // ---- prefetch window 0 ----
    float2 kv = *reinterpret_cast<const float2*>(
        &g_k[(row0 + ptok) * (HK * DK) + hk * DK + ppos]);
    float2 qv = *reinterpret_cast<const float2*>(
        &g_q[(row0 + ptok) * (HK * DK) + hk * DK + ppos]);
    float  vp[4]; float2 gbp[4];
    #pragma unroll
    for (int i = 0; i < 4; i++) {
        vp[i]  = g_v[(row0 + i) * (HV * DV) + h * DV + col];
        gbp[i] = g_gb[(row0 + i) * HV + h];
    }
    size_t dtb = ((row0 >> 2) * HK + hk) * 4;   // float4 index into g_dt
    const float4* dtp = reinterpret_cast<const float4*>(g_dt);
    float4 T0 = dtp[dtb], T1 = dtp[dtb + 1], T2 = dtp[dtb + 2], T3 = dtp[dtb + 3];

    for (int w = 0; w < SEQ / 4; w++) {
        const int pb = w & 1;
        *reinterpret_cast<float2*>(&ksh[pb][psmem]) = kv;
        *reinterpret_cast<float2*>(&qsh[pb][psmem]) = qv;
        const float v0 = vp[0], v1 = vp[1], v2 = vp[2], v3 = vp[3];
        const float d0 = gbp[0].x, d1 = gbp[1].x, d2 = gbp[2].x, d3 = gbp[3].x;
        const float b0 = gbp[0].y, b1 = gbp[1].y, b2 = gbp[2].y, b3 = gbp[3].y;
        const float4 A0 = T0, A1 = T1, A2 = T2, A3 = T3;
        __syncthreads();

        // ---- prefetch window w+1 (lands during compute) ----
        if (w + 1 < SEQ / 4) {
            const size_t tn = row0 + (size_t)(w + 1) * 4;
            kv = *reinterpret_cast<const float2*>(
                &g_k[(tn + ptok) * (HK * DK) + hk * DK + ppos]);
            qv = *reinterpret_cast<const float2*>(
                &g_q[(tn + ptok) * (HK * DK) + hk * DK + ppos]);
            #pragma unroll
            for (int i = 0; i < 4; i++) {
                vp[i]  = g_v[(tn + i) * (HV * DV) + h * DV + col];
                gbp[i] = g_gb[(tn + i) * HV + h];
            }
            dtb += HK * 4;
            T0 = dtp[dtb]; T1 = dtp[dtb + 1]; T2 = dtp[dtb + 2]; T3 = dtp[dtb + 3];
        }

        const float* kb = &ksh[pb][rp * 36];
        const float* qb = &qsh[pb][rp * 36];

        // ---- dot pass: kp[i] = k_i[rows].S0, qp[i] = q_i[rows].S0 ----
        float kp[4] = {0.f, 0.f, 0.f, 0.f};
        float qp[4] = {0.f, 0.f, 0.f, 0.f};
        #pragma unroll
        for (int r = 0; r < 8; r++) {
            const float s0 = S[4*r], s1 = S[4*r+1], s2 = S[4*r+2], s3 = S[4*r+3];
            #pragma unroll
            for (int i = 0; i < 4; i++) {
                const float4 kk = *reinterpret_cast<const float4*>(&kb[i * 144 + 4 * r]);
                const float4 qq = *reinterpret_cast<const float4*>(&qb[i * 144 + 4 * r]);
                kp[i] += kk.x * s0 + kk.y * s1 + kk.z * s2 + kk.w * s3;
                qp[i] += qq.x * s0 + qq.y * s1 + qq.z * s2 + qq.w * s3;
            }
        }
        #pragma unroll
        for (int i = 0; i < 4; i++) {
            kp[i] += __shfl_xor_sync(~0u, kp[i], 1);
            kp[i] += __shfl_xor_sync(~0u, kp[i], 2);
            qp[i] += __shfl_xor_sync(~0u, qp[i], 1);
            qp[i] += __shfl_xor_sync(~0u, qp[i], 2);
        }

        // ---- scalar window recurrence (per column; forward products only) ----
        const float D1 = d0, D2 = D1 * d1, D3 = D2 * d2, D4 = D3 * d3;
        const float f12 = d1, f23 = d2, f34 = d3;
        const float f13 = d1 * d2, f24 = d2 * d3;
        const float f14 = f13 * d3;
        const float u1 = b0 * (v0 - d0 * kp[0]);
        const float u2 = b1 * (v1 - d1 * (D1 * kp[1] + A0.x * u1));
        const float u3 = b2 * (v2 - d2 * (D2 * kp[2] + f12 * A0.y * u1 + A0.z * u2));
        const float u4 = b3 * (v3 - d3 * (D3 * kp[3] + f13 * A0.w * u1
                                          + f23 * A1.x * u2 + A1.y * u3));
        const float o1 = (D1 * qp[0] + A1.z * u1) * scale;
        const float o2 = (D2 * qp[1] + f12 * A1.w * u1 + A2.x * u2) * scale;
        const float o3 = (D3 * qp[2] + f13 * A2.y * u1 + f23 * A2.z * u2
                          + A2.w * u3) * scale;
        const float o4 = (D4 * qp[3] + f14 * A3.x * u1 + f24 * A3.y * u2
                          + f34 * A3.z * u3 + A3.w * u4) * scale;
        const float e1 = f14 * u1, e2 = f24 * u2, e3 = f34 * u3, e4 = u4;

        // ---- fused rank-4 update: S = D4*S + k1*e1 + k2*e2 + k3*e3 + k4*e4 ----
        #pragma unroll
        for (int r = 0; r < 8; r++) {
            const float4 k1 = *reinterpret_cast<const float4*>(&kb[0 * 144 + 4 * r]);
            const float4 k2 = *reinterpret_cast<const float4*>(&kb[1 * 144 + 4 * r]);
            const float4 k3 = *reinterpret_cast<const float4*>(&kb[2 * 144 + 4 * r]);
            const float4 k4 = *reinterpret_cast<const float4*>(&kb[3 * 144 + 4 * r]);
            S[4*r  ] = S[4*r  ] * D4 + k1.x * e1 + k2.x * e2 + k3.x * e3 + k4.x * e4;
            S[4*r+1] = S[4*r+1] * D4 + k1.y * e1 + k2.y * e2 + k3.y * e3 + k4.y * e4;
            S[4*r+2] = S[4*r+2] * D4 + k1.z * e1 + k2.z * e2 + k3.z * e3 + k4.z * e4;
            S[4*r+3] = S[4*r+3] * D4 + k1.w * e1 + k2.w * e2 + k3.w * e3 + k4.w * e4;
        }

        // ---- output: lane rp writes token w*4+rp (all lanes hold all o's) ----
        const float osel = (rp == 0) ? o1 : (rp == 1) ? o2 : (rp == 2) ? o3 : o4;
        out[((row0 + (size_t)w * 4 + rp) * HV + h) * DV + col] = osel;
    }
}

// ---------------- launch ------------------------------------------------------
extern "C" void kernel_launch(void* const* d_in, const int* in_sizes, int n_in,
                              void* d_out, int out_size)
{
    const float* x    = (const float*)d_in[0];  // mixed_qkv [4096, 8192]
    const float* b    = (const float*)d_in[1];  // [4096, 32]
    const float* a    = (const float*)d_in[2];  // [4096, 32]
    const float* w    = (const float*)d_in[3];  // conv_weights [8192, 4]
    const float* dt   = (const float*)d_in[4];  // [32]
    const float* alog = (const float*)d_in[5];  // [32]
    // d_in[6] = cu_seqlens (equal-length; unused)

    conv_kernel<<<dim3(NTOK / TT, 64), 128>>>(x, w);
    gate_kernel<<<(NTOK * HV + 255) / 256, 256>>>(b, a, dt, alog);
    dot_kernel<<<dim3(NW / 4, HK), 128>>>();
    scan_kernel<<<128, 256>>>((float*)d_out);
}

// round 7
// speedup vs baseline: 4.1676x; 1.5180x over previous
#include <cuda_runtime.h>
#include <math.h>

#define BB   2
#define SEQ  2048
#define HK   16
#define HV   32
#define DK   128
#define DV   128
#define QKV  8192
#define NTOK (BB*SEQ)
#define EPSF 1e-6f
#define TT   8          // tokens per conv block
#define NW   (NTOK/4)   // 4-token windows

// smem token layout: 8 chunks of (16 floats + 4 pad) = 160 floats per token
#define TOKSTRIDE 160

// ---------------- scratch (device globals: allocation-free) ----------------
__device__ float  g_q[NTOK * HK * DK];
__device__ float  g_k[NTOK * HK * DK];
__device__ float  g_v[NTOK * HV * DV];
__device__ float2 g_gb[NTOK * HV];            // (exp(g), beta)
__device__ float  g_dt[NW * HK * 16];         // per-window pairwise dot table

// ---------------- kernel 1: causal conv + SiLU + l2norm, 8 tokens/block -----
__global__ __launch_bounds__(128) void conv_kernel(
    const float* __restrict__ x, const float* __restrict__ w)
{
    const int tile = blockIdx.x;
    const int slot = blockIdx.y;
    const int tid  = threadIdx.x;
    const int ch   = slot * 128 + tid;
    const int t0   = tile * TT;
    const int s0   = t0 & (SEQ - 1);

    const float4 wv = reinterpret_cast<const float4*>(w)[ch];

    float xv[TT + 3];
    #pragma unroll
    for (int j = 0; j < TT + 3; j++) {
        const int off = j - 3;
        xv[j] = (s0 + off >= 0) ? x[(size_t)(t0 + off) * QKV + ch] : 0.0f;
    }

    float y[TT];
    #pragma unroll
    for (int j = 0; j < TT; j++) {
        float acc = wv.x * xv[j] + wv.y * xv[j + 1] + wv.z * xv[j + 2] + wv.w * xv[j + 3];
        y[j] = acc / (1.0f + __expf(-acc));   // SiLU
    }

    if (slot < 32) {
        float ss[TT];
        #pragma unroll
        for (int j = 0; j < TT; j++) ss[j] = y[j] * y[j];
        #pragma unroll
        for (int o = 16; o; o >>= 1) {
            #pragma unroll
            for (int j = 0; j < TT; j++) ss[j] += __shfl_xor_sync(0xffffffffu, ss[j], o);
        }
        __shared__ float red[4][TT];
        if ((tid & 31) == 0) {
            #pragma unroll
            for (int j = 0; j < TT; j++) red[tid >> 5][j] = ss[j];
        }
        __syncthreads();
        #pragma unroll
        for (int j = 0; j < TT; j++) {
            float tot = red[0][j] + red[1][j] + red[2][j] + red[3][j];
            y[j] *= rsqrtf(tot + EPSF);
        }
        if (slot < 16) {
            #pragma unroll
            for (int j = 0; j < TT; j++)
                g_q[(size_t)(t0 + j) * HK * DK + slot * DK + tid] = y[j];
        } else {
            #pragma unroll
            for (int j = 0; j < TT; j++)
                g_k[(size_t)(t0 + j) * HK * DK + (slot - 16) * DK + tid] = y[j];
        }
    } else {
        #pragma unroll
        for (int j = 0; j < TT; j++)
            g_v[(size_t)(t0 + j) * HV * DV + (slot - 32) * DV + tid] = y[j];
    }
}

// ---------------- kernel 2: gating precompute --------------------------------
__global__ void gate_kernel(const float* __restrict__ b_in,
                            const float* __restrict__ a_in,
                            const float* __restrict__ dt_bias,
                            const float* __restrict__ alog)
{
    int i = blockIdx.x * blockDim.x + threadIdx.x;
    if (i >= NTOK * HV) return;
    int h = i & (HV - 1);
    float xx = a_in[i] + dt_bias[h];
    float sp = fmaxf(xx, 0.0f) + log1pf(expf(-fabsf(xx)));
    float g  = -expf(alog[h]) * sp;
    float eg = expf(g);
    float bb = b_in[i];
    float beta = 1.0f / (1.0f + expf(-bb));
    g_gb[i] = make_float2(eg, beta);
}

// ---------------- kernel 2.5: per-window pairwise dot table ------------------
__device__ __forceinline__ float dot4(float4 a, float4 b) {
    return a.x*b.x + a.y*b.y + a.z*b.z + a.w*b.w;
}
__global__ __launch_bounds__(128) void dot_kernel()
{
    const int warp = threadIdx.x >> 5;
    const int lane = threadIdx.x & 31;
    const int w    = blockIdx.x * 4 + warp;
    const int hk   = blockIdx.y;

    const size_t base = (size_t)(w * 4) * (HK * DK) + hk * DK + lane * 4;
    float4 k[4], q[4];
    #pragma unroll
    for (int i = 0; i < 4; i++) {
        k[i] = *reinterpret_cast<const float4*>(&g_k[base + (size_t)i * (HK * DK)]);
        q[i] = *reinterpret_cast<const float4*>(&g_q[base + (size_t)i * (HK * DK)]);
    }
    float s0  = dot4(k[1], k[0]), s1  = dot4(k[2], k[0]), s2  = dot4(k[2], k[1]);
    float s3  = dot4(k[3], k[0]), s4  = dot4(k[3], k[1]), s5  = dot4(k[3], k[2]);
    float s6  = dot4(q[0], k[0]), s7  = dot4(q[1], k[0]), s8  = dot4(q[1], k[1]);
    float s9  = dot4(q[2], k[0]), s10 = dot4(q[2], k[1]), s11 = dot4(q[2], k[2]);
    float s12 = dot4(q[3], k[0]), s13 = dot4(q[3], k[1]), s14 = dot4(q[3], k[2]);
    float s15 = dot4(q[3], k[3]);
    #pragma unroll
    for (int o = 16; o; o >>= 1) {
        s0  += __shfl_xor_sync(~0u, s0,  o); s1  += __shfl_xor_sync(~0u, s1,  o);
        s2  += __shfl_xor_sync(~0u, s2,  o); s3  += __shfl_xor_sync(~0u, s3,  o);
        s4  += __shfl_xor_sync(~0u, s4,  o); s5  += __shfl_xor_sync(~0u, s5,  o);
        s6  += __shfl_xor_sync(~0u, s6,  o); s7  += __shfl_xor_sync(~0u, s7,  o);
        s8  += __shfl_xor_sync(~0u, s8,  o); s9  += __shfl_xor_sync(~0u, s9,  o);
        s10 += __shfl_xor_sync(~0u, s10, o); s11 += __shfl_xor_sync(~0u, s11, o);
        s12 += __shfl_xor_sync(~0u, s12, o); s13 += __shfl_xor_sync(~0u, s13, o);
        s14 += __shfl_xor_sync(~0u, s14, o); s15 += __shfl_xor_sync(~0u, s15, o);
    }
    if (lane == 0) {
        float4* p = reinterpret_cast<float4*>(&g_dt[(size_t)(w * HK + hk) * 16]);
        p[0] = make_float4(s0,  s1,  s2,  s3);
        p[1] = make_float4(s4,  s5,  s6,  s7);
        p[2] = make_float4(s8,  s9,  s10, s11);
        p[3] = make_float4(s12, s13, s14, s15);
    }
}

// ---------------- kernel 3: windowed gated delta-rule scan --------------------
// grid: 128 (= B*HV * 2 column-halves), block: 256 (8 warps).
// Each thread owns 16 rows x 2 cols of state (rp = lane>>2 picks rows
// [rp*16, rp*16+16), col pair = (warp*4 + (lane&3)) * 2 within the half).
// Per window: 8 independent dots vs S0 (2 cols amortize each k/q smem read),
// scalar window recurrence per column, fused rank-4 update.
__global__ __launch_bounds__(256, 1) void scan_kernel(float* __restrict__ out)
{
    const int blk  = blockIdx.x;
    const int bh   = blk >> 1;
    const int half = blk & 1;
    const int bb   = bh / HV;
    const int h    = bh % HV;
    const int hk   = h >> 1;              // GQA
    const int tid  = threadIdx.x;
    const int lane = tid & 31;
    const int warp = tid >> 5;
    const int rp   = lane >> 2;                   // 0..7 row partition
    const int cg   = warp * 4 + (lane & 3);       // 0..31 col pair
    const int col0 = half * 64 + cg * 2;
    const float scale = 0.08838834764831845f;     // 128^-0.5

    __shared__ __align__(16) float ksh[2][4 * TOKSTRIDE];
    __shared__ __align__(16) float qsh[2][4 * TOKSTRIDE];

    float S[32];                                  // S[rr*2 + c], rr=0..15
    #pragma unroll
    for (int i = 0; i < 32; i++) S[i] = 0.0f;

    const size_t row0 = (size_t)bb * SEQ;

    // staging role: thread stages 2 consecutive floats of one token's k and q
    const int ptok  = tid >> 6;                   // 0..3
    const int ppos  = (tid & 63) * 2;             // 0..126
    const int psmem = ptok * TOKSTRIDE + (ppos >> 4) * 20 + (ppos & 15);

    // ---- prefetch window 0 ----
    float2 kv = *reinterpret_cast<const float2*>(
        &g_k[(row0 + ptok) * (HK * DK) + hk * DK + ppos]);
    float2 qv = *reinterpret_cast<const float2*>(
        &g_q[(row0 + ptok) * (HK * DK) + hk * DK + ppos]);
    float2 vp[4]; float2 gbp[4];
    #pragma unroll
    for (int i = 0; i < 4; i++) {
        vp[i]  = *reinterpret_cast<const float2*>(
            &g_v[(row0 + i) * (HV * DV) + h * DV + col0]);
        gbp[i] = g_gb[(row0 + i) * HV + h];
    }
    size_t dtb = ((row0 >> 2) * HK + hk) * 4;     // float4 index into g_dt
    const float4* dtp = reinterpret_cast<const float4*>(g_dt);
    float4 T0 = dtp[dtb], T1 = dtp[dtb + 1], T2 = dtp[dtb + 2], T3 = dtp[dtb + 3];

    for (int w = 0; w < SEQ / 4; w++) {
        const int pb = w & 1;
        *reinterpret_cast<float2*>(&ksh[pb][psmem]) = kv;
        *reinterpret_cast<float2*>(&qsh[pb][psmem]) = qv;
        const float2 v0 = vp[0], v1 = vp[1], v2 = vp[2], v3 = vp[3];
        const float d0 = gbp[0].x, d1 = gbp[1].x, d2 = gbp[2].x, d3 = gbp[3].x;
        const float b0 = gbp[0].y, b1 = gbp[1].y, b2 = gbp[2].y, b3 = gbp[3].y;
        const float4 A0 = T0, A1 = T1, A2 = T2, A3 = T3;
        __syncthreads();

        // ---- prefetch window w+1 ----
        if (w + 1 < SEQ / 4) {
            const size_t tn = row0 + (size_t)(w + 1) * 4;
            kv = *reinterpret_cast<const float2*>(
                &g_k[(tn + ptok) * (HK * DK) + hk * DK + ppos]);
            qv = *reinterpret_cast<const float2*>(
                &g_q[(tn + ptok) * (HK * DK) + hk * DK + ppos]);
            #pragma unroll
            for (int i = 0; i < 4; i++) {
                vp[i]  = *reinterpret_cast<const float2*>(
                    &g_v[(tn + i) * (HV * DV) + h * DV + col0]);
                gbp[i] = g_gb[(tn + i) * HV + h];
            }
            dtb += HK * 4;
            T0 = dtp[dtb]; T1 = dtp[dtb + 1]; T2 = dtp[dtb + 2]; T3 = dtp[dtb + 3];
        }

        const float* kb = &ksh[pb][rp * 20];      // my 16-row chunk, token stride 160
        const float* qb = &qsh[pb][rp * 20];

        // ---- dot pass: kp[i*2+c] = k_i[rows].S0[:,c], qp likewise ----
        float kp[8], qp[8];
        #pragma unroll
        for (int i = 0; i < 8; i++) { kp[i] = 0.0f; qp[i] = 0.0f; }
        #pragma unroll
        for (int i = 0; i < 4; i++) {
            #pragma unroll
            for (int r = 0; r < 4; r++) {
                const float4 kk = *reinterpret_cast<const float4*>(&kb[i * TOKSTRIDE + 4 * r]);
                const float4 qq = *reinterpret_cast<const float4*>(&qb[i * TOKSTRIDE + 4 * r]);
                const int s = 8 * r;  // S index of row 4r, col 0
                kp[i*2+0] += kk.x * S[s+0] + kk.y * S[s+2] + kk.z * S[s+4] + kk.w * S[s+6];
                kp[i*2+1] += kk.x * S[s+1] + kk.y * S[s+3] + kk.z * S[s+5] + kk.w * S[s+7];
                qp[i*2+0] += qq.x * S[s+0] + qq.y * S[s+2] + qq.z * S[s+4] + qq.w * S[s+6];
                qp[i*2+1] += qq.x * S[s+1] + qq.y * S[s+3] + qq.z * S[s+5] + qq.w * S[s+7];
            }
        }
        // reduce across the 8 row partitions (lane bits 2,3,4)
        #pragma unroll
        for (int i = 0; i < 8; i++) {
            kp[i] += __shfl_xor_sync(~0u, kp[i], 4);
            kp[i] += __shfl_xor_sync(~0u, kp[i], 8);
            kp[i] += __shfl_xor_sync(~0u, kp[i], 16);
            qp[i] += __shfl_xor_sync(~0u, qp[i], 4);
            qp[i] += __shfl_xor_sync(~0u, qp[i], 8);
            qp[i] += __shfl_xor_sync(~0u, qp[i], 16);
        }

        // ---- scalar window recurrence, per column ----
        const float D1 = d0, D2 = D1 * d1, D3 = D2 * d2, D4 = D3 * d3;
        const float f12 = d1, f23 = d2, f34 = d3;
        const float f13 = d1 * d2, f24 = d2 * d3;
        const float f14 = f13 * d3;
        float u1[2], u2[2], u3[2], u4[2], o1[2], o2[2], o3[2], o4[2];
        float e1[2], e2[2], e3[2], e4[2];
        const float vv0[2] = {v0.x, v0.y}, vv1[2] = {v1.x, v1.y};
        const float vv2[2] = {v2.x, v2.y}, vv3[2] = {v3.x, v3.y};
        #pragma unroll
        for (int c = 0; c < 2; c++) {
            u1[c] = b0 * (vv0[c] - d0 * kp[0*2+c]);
            u2[c] = b1 * (vv1[c] - d1 * (D1 * kp[1*2+c] + A0.x * u1[c]));
            u3[c] = b2 * (vv2[c] - d2 * (D2 * kp[2*2+c] + f12 * A0.y * u1[c] + A0.z * u2[c]));
            u4[c] = b3 * (vv3[c] - d3 * (D3 * kp[3*2+c] + f13 * A0.w * u1[c]
                                         + f23 * A1.x * u2[c] + A1.y * u3[c]));
            o1[c] = (D1 * qp[0*2+c] + A1.z * u1[c]) * scale;
            o2[c] = (D2 * qp[1*2+c] + f12 * A1.w * u1[c] + A2.x * u2[c]) * scale;
            o3[c] = (D3 * qp[2*2+c] + f13 * A2.y * u1[c] + f23 * A2.z * u2[c]
                     + A2.w * u3[c]) * scale;
            o4[c] = (D4 * qp[3*2+c] + f14 * A3.x * u1[c] + f24 * A3.y * u2[c]
                     + f34 * A3.z * u3[c] + A3.w * u4[c]) * scale;
            e1[c] = f14 * u1[c]; e2[c] = f24 * u2[c]; e3[c] = f34 * u3[c]; e4[c] = u4[c];
        }

        // ---- fused rank-4 update: S = D4*S + sum_j k_j * e_j ----
        #pragma unroll
        for (int r = 0; r < 4; r++) {
            const float4 k1 = *reinterpret_cast<const float4*>(&kb[0 * TOKSTRIDE + 4 * r]);
            const float4 k2 = *reinterpret_cast<const float4*>(&kb[1 * TOKSTRIDE + 4 * r]);
            const float4 k3 = *reinterpret_cast<const float4*>(&kb[2 * TOKSTRIDE + 4 * r]);
            const float4 k4 = *reinterpret_cast<const float4*>(&kb[3 * TOKSTRIDE + 4 * r]);
            const int s = 8 * r;
            #pragma unroll
            for (int c = 0; c < 2; c++) {
                S[s+0+c] = S[s+0+c] * D4 + k1.x * e1[c] + k2.x * e2[c] + k3.x * e3[c] + k4.x * e4[c];
                S[s+2+c] = S[s+2+c] * D4 + k1.y * e1[c] + k2.y * e2[c] + k3.y * e3[c] + k4.y * e4[c];
                S[s+4+c] = S[s+4+c] * D4 + k1.z * e1[c] + k2.z * e2[c] + k3.z * e3[c] + k4.z * e4[c];
                S[s+6+c] = S[s+6+c] * D4 + k1.w * e1[c] + k2.w * e2[c] + k3.w * e3[c] + k4.w * e4[c];
            }
        }

        // ---- output: rp 0..3 writes token w*4+rp, both cols (float2) ----
        if (rp < 4) {
            const float ox = (rp == 0) ? o1[0] : (rp == 1) ? o2[0] : (rp == 2) ? o3[0] : o4[0];
            const float oy = (rp == 0) ? o1[1] : (rp == 1) ? o2[1] : (rp == 2) ? o3[1] : o4[1];
            *reinterpret_cast<float2*>(
                &out[((row0 + (size_t)w * 4 + rp) * HV + h) * DV + col0]) = make_float2(ox, oy);
        }
    }
}

// ---------------- launch ------------------------------------------------------
extern "C" void kernel_launch(void* const* d_in, const int* in_sizes, int n_in,
                              void* d_out, int out_size)
{
    const float* x    = (const float*)d_in[0];  // mixed_qkv [4096, 8192]
    const float* b    = (const float*)d_in[1];  // [4096, 32]
    const float* a    = (const float*)d_in[2];  // [4096, 32]
    const float* w    = (const float*)d_in[3];  // conv_weights [8192, 4]
    const float* dt   = (const float*)d_in[4];  // [32]
    const float* alog = (const float*)d_in[5];  // [32]
    // d_in[6] = cu_seqlens (equal-length; unused)

    conv_kernel<<<dim3(NTOK / TT, 64), 128>>>(x, w);
    gate_kernel<<<(NTOK * HV + 255) / 256, 256>>>(b, a, dt, alog);
    dot_kernel<<<dim3(NW / 4, HK), 128>>>();
    scan_kernel<<<128, 256>>>((float*)d_out);
}

// round 9
// speedup vs baseline: 4.6381x; 1.1129x over previous
#include <cuda_runtime.h>
#include <math.h>

#define BB   2
#define SEQ  2048
#define HK   16
#define HV   32
#define DK   128
#define DV   128
#define QKV  8192
#define NTOK (BB*SEQ)
#define EPSF 1e-6f
#define TT   8          // tokens per conv block
#define NW   (NTOK/4)   // 4-token windows

// smem token layout: 8 chunks of (16 floats + 4 pad) = 160 floats per token
#define TOKSTRIDE 160

typedef unsigned long long ull;

// ---------------- packed f32x2 helpers (Blackwell) ----------------
__device__ __forceinline__ ull fma2(ull a, ull b, ull c) {
    ull d; asm("fma.rn.f32x2 %0, %1, %2, %3;" : "=l"(d) : "l"(a), "l"(b), "l"(c)); return d;
}
__device__ __forceinline__ ull mul2(ull a, ull b) {
    ull d; asm("mul.rn.f32x2 %0, %1, %2;" : "=l"(d) : "l"(a), "l"(b)); return d;
}
__device__ __forceinline__ ull pack2(float lo, float hi) {
    ull d; asm("mov.b64 %0, {%1, %2};" : "=l"(d)
               : "r"(__float_as_uint(lo)), "r"(__float_as_uint(hi))); return d;
}
__device__ __forceinline__ float hadd2(ull a) {
    unsigned lo, hi; asm("mov.b64 {%0, %1}, %2;" : "=r"(lo), "=r"(hi) : "l"(a));
    return __uint_as_float(lo) + __uint_as_float(hi);
}

// ---------------- scratch (device globals: allocation-free) ----------------
__device__ float  g_q[NTOK * HK * DK];
__device__ float  g_k[NTOK * HK * DK];
__device__ float  g_v[NTOK * HV * DV];
__device__ float2 g_gb[NTOK * HV];            // (exp(g), beta)
__device__ float  g_dt[NW * HK * 16];         // per-window pairwise dot table

// ---------------- kernel 1: causal conv + SiLU + l2norm, 8 tokens/block -----
__global__ __launch_bounds__(128) void conv_kernel(
    const float* __restrict__ x, const float* __restrict__ w)
{
    const int tile = blockIdx.x;
    const int slot = blockIdx.y;
    const int tid  = threadIdx.x;
    const int ch   = slot * 128 + tid;
    const int t0   = tile * TT;
    const int s0   = t0 & (SEQ - 1);

    const float4 wv = reinterpret_cast<const float4*>(w)[ch];

    float xv[TT + 3];
    #pragma unroll
    for (int j = 0; j < TT + 3; j++) {
        const int off = j - 3;
        xv[j] = (s0 + off >= 0) ? x[(size_t)(t0 + off) * QKV + ch] : 0.0f;
    }

    float y[TT];
    #pragma unroll
    for (int j = 0; j < TT; j++) {
        float acc = wv.x * xv[j] + wv.y * xv[j + 1] + wv.z * xv[j + 2] + wv.w * xv[j + 3];
        y[j] = acc / (1.0f + __expf(-acc));   // SiLU
    }

    if (slot < 32) {
        float ss[TT];
        #pragma unroll
        for (int j = 0; j < TT; j++) ss[j] = y[j] * y[j];
        #pragma unroll
        for (int o = 16; o; o >>= 1) {
            #pragma unroll
            for (int j = 0; j < TT; j++) ss[j] += __shfl_xor_sync(0xffffffffu, ss[j], o);
        }
        __shared__ float red[4][TT];
        if ((tid & 31) == 0) {
            #pragma unroll
            for (int j = 0; j < TT; j++) red[tid >> 5][j] = ss[j];
        }
        __syncthreads();
        #pragma unroll
        for (int j = 0; j < TT; j++) {
            float tot = red[0][j] + red[1][j] + red[2][j] + red[3][j];
            y[j] *= rsqrtf(tot + EPSF);
        }
        if (slot < 16) {
            #pragma unroll
            for (int j = 0; j < TT; j++)
                g_q[(size_t)(t0 + j) * HK * DK + slot * DK + tid] = y[j];
        } else {
            #pragma unroll
            for (int j = 0; j < TT; j++)
                g_k[(size_t)(t0 + j) * HK * DK + (slot - 16) * DK + tid] = y[j];
        }
    } else {
        #pragma unroll
        for (int j = 0; j < TT; j++)
            g_v[(size_t)(t0 + j) * HV * DV + (slot - 32) * DV + tid] = y[j];
    }
}

// ---------------- kernel 2: gating precompute --------------------------------
__global__ void gate_kernel(const float* __restrict__ b_in,
                            const float* __restrict__ a_in,
                            const float* __restrict__ dt_bias,
                            const float* __restrict__ alog)
{
    int i = blockIdx.x * blockDim.x + threadIdx.x;
    if (i >= NTOK * HV) return;
    int h = i & (HV - 1);
    float xx = a_in[i] + dt_bias[h];
    float sp = fmaxf(xx, 0.0f) + log1pf(expf(-fabsf(xx)));
    float g  = -expf(alog[h]) * sp;
    float eg = expf(g);
    float bb = b_in[i];
    float beta = 1.0f / (1.0f + expf(-bb));
    g_gb[i] = make_float2(eg, beta);
}

// ---------------- kernel 2.5: per-window pairwise dot table ------------------
__device__ __forceinline__ float dot4(float4 a, float4 b) {
    return a.x*b.x + a.y*b.y + a.z*b.z + a.w*b.w;
}
__global__ __launch_bounds__(128) void dot_kernel()
{
    const int warp = threadIdx.x >> 5;
    const int lane = threadIdx.x & 31;
    const int w    = blockIdx.x * 4 + warp;
    const int hk   = blockIdx.y;

    const size_t base = (size_t)(w * 4) * (HK * DK) + hk * DK + lane * 4;
    float4 k[4], q[4];
    #pragma unroll
    for (int i = 0; i < 4; i++) {
        k[i] = *reinterpret_cast<const float4*>(&g_k[base + (size_t)i * (HK * DK)]);
        q[i] = *reinterpret_cast<const float4*>(&g_q[base + (size_t)i * (HK * DK)]);
    }
    float s0  = dot4(k[1], k[0]), s1  = dot4(k[2], k[0]), s2  = dot4(k[2], k[1]);
    float s3  = dot4(k[3], k[0]), s4  = dot4(k[3], k[1]), s5  = dot4(k[3], k[2]);
    float s6  = dot4(q[0], k[0]), s7  = dot4(q[1], k[0]), s8  = dot4(q[1], k[1]);
    float s9  = dot4(q[2], k[0]), s10 = dot4(q[2], k[1]), s11 = dot4(q[2], k[2]);
    float s12 = dot4(q[3], k[0]), s13 = dot4(q[3], k[1]), s14 = dot4(q[3], k[2]);
    float s15 = dot4(q[3], k[3]);
    #pragma unroll
    for (int o = 16; o; o >>= 1) {
        s0  += __shfl_xor_sync(~0u, s0,  o); s1  += __shfl_xor_sync(~0u, s1,  o);
        s2  += __shfl_xor_sync(~0u, s2,  o); s3  += __shfl_xor_sync(~0u, s3,  o);
        s4  += __shfl_xor_sync(~0u, s4,  o); s5  += __shfl_xor_sync(~0u, s5,  o);
        s6  += __shfl_xor_sync(~0u, s6,  o); s7  += __shfl_xor_sync(~0u, s7,  o);
        s8  += __shfl_xor_sync(~0u, s8,  o); s9  += __shfl_xor_sync(~0u, s9,  o);
        s10 += __shfl_xor_sync(~0u, s10, o); s11 += __shfl_xor_sync(~0u, s11, o);
        s12 += __shfl_xor_sync(~0u, s12, o); s13 += __shfl_xor_sync(~0u, s13, o);
        s14 += __shfl_xor_sync(~0u, s14, o); s15 += __shfl_xor_sync(~0u, s15, o);
    }
    if (lane == 0) {
        float4* p = reinterpret_cast<float4*>(&g_dt[(size_t)(w * HK + hk) * 16]);
        p[0] = make_float4(s0,  s1,  s2,  s3);
        p[1] = make_float4(s4,  s5,  s6,  s7);
        p[2] = make_float4(s8,  s9,  s10, s11);
        p[3] = make_float4(s12, s13, s14, s15);
    }
}

// ---------------- kernel 3: windowed gated delta-rule scan (f32x2 core) ------
// grid: 128 (= B*HV * 2 column-halves), block: 256 (8 warps).
// Thread owns 16 rows x 2 cols; state packed as 8 row-pairs x 2 cols of
// f32x2 (adjacent rows, same column). k/q row-pairs read from smem as b64,
// so the packed dot/update passes need ~no pack instructions.
__global__ __launch_bounds__(256, 1) void scan_kernel(float* __restrict__ out)
{
    const int blk  = blockIdx.x;
    const int bh   = blk >> 1;
    const int half = blk & 1;
    const int bb   = bh / HV;
    const int h    = bh % HV;
    const int hk   = h >> 1;              // GQA
    const int tid  = threadIdx.x;
    const int lane = tid & 31;
    const int warp = tid >> 5;
    const int rp   = lane >> 2;                   // 0..7 row partition (16 rows)
    const int cg   = warp * 4 + (lane & 3);       // 0..31 col pair
    const int col0 = half * 64 + cg * 2;
    const float scale = 0.08838834764831845f;     // 128^-0.5

    __shared__ __align__(16) float ksh[2][4 * TOKSTRIDE];
    __shared__ __align__(16) float qsh[2][4 * TOKSTRIDE];

    // S2[rr*2 + c] = f32x2 over rows (2rr, 2rr+1) of column c, rr = 0..7
    ull S2[16];
    #pragma unroll
    for (int i = 0; i < 16; i++) S2[i] = 0ull;

    const size_t row0 = (size_t)bb * SEQ;

    // staging role: thread stages 2 consecutive floats of one token's k and q
    const int ptok  = tid >> 6;                   // 0..3
    const int ppos  = (tid & 63) * 2;             // 0..126
    const int psmem = ptok * TOKSTRIDE + (ppos >> 4) * 20 + (ppos & 15);

    // ---- prefetch window 0 ----
    float2 kv = *reinterpret_cast<const float2*>(
        &g_k[(row0 + ptok) * (HK * DK) + hk * DK + ppos]);
    float2 qv = *reinterpret_cast<const float2*>(
        &g_q[(row0 + ptok) * (HK * DK) + hk * DK + ppos]);
    float2 vp[4]; float2 gbp[4];
    #pragma unroll
    for (int i = 0; i < 4; i++) {
        vp[i]  = *reinterpret_cast<const float2*>(
            &g_v[(row0 + i) * (HV * DV) + h * DV + col0]);
        gbp[i] = g_gb[(row0 + i) * HV + h];
    }
    size_t dtb = ((row0 >> 2) * HK + hk) * 4;     // float4 index into g_dt
    const float4* dtp = reinterpret_cast<const float4*>(g_dt);
    float4 T0 = dtp[dtb], T1 = dtp[dtb + 1], T2 = dtp[dtb + 2], T3 = dtp[dtb + 3];

    for (int w = 0; w < SEQ / 4; w++) {
        const int pb = w & 1;
        *reinterpret_cast<float2*>(&ksh[pb][psmem]) = kv;
        *reinterpret_cast<float2*>(&qsh[pb][psmem]) = qv;
        const float2 v0 = vp[0], v1 = vp[1], v2 = vp[2], v3 = vp[3];
        const float d0 = gbp[0].x, d1 = gbp[1].x, d2 = gbp[2].x, d3 = gbp[3].x;
        const float b0 = gbp[0].y, b1 = gbp[1].y, b2 = gbp[2].y, b3 = gbp[3].y;
        const float4 A0 = T0, A1 = T1, A2 = T2, A3 = T3;
        __syncthreads();

        // ---- prefetch window w+1 ----
        if (w + 1 < SEQ / 4) {
            const size_t tn = row0 + (size_t)(w + 1) * 4;
            kv = *reinterpret_cast<const float2*>(
                &g_k[(tn + ptok) * (HK * DK) + hk * DK + ppos]);
            qv = *reinterpret_cast<const float2*>(
                &g_q[(tn + ptok) * (HK * DK) + hk * DK + ppos]);
            #pragma unroll
            for (int i = 0; i < 4; i++) {
                vp[i]  = *reinterpret_cast<const float2*>(
                    &g_v[(tn + i) * (HV * DV) + h * DV + col0]);
                gbp[i] = g_gb[(tn + i) * HV + h];
            }
            dtb += HK * 4;
            T0 = dtp[dtb]; T1 = dtp[dtb + 1]; T2 = dtp[dtb + 2]; T3 = dtp[dtb + 3];
        }

        const float* kb = &ksh[pb][rp * 20];      // my 16-row chunk
        const float* qb = &qsh[pb][rp * 20];

        // ---- packed dot pass: kp2[i*2+c] accumulates k_i(row-pairs).S0[:,c]
        ull kp2[8], qp2[8];
        #pragma unroll
        for (int i = 0; i < 8; i++) { kp2[i] = 0ull; qp2[i] = 0ull; }
        #pragma unroll
        for (int i = 0; i < 4; i++) {
            const ulonglong2* kt = reinterpret_cast<const ulonglong2*>(kb + i * TOKSTRIDE);
            const ulonglong2* qt = reinterpret_cast<const ulonglong2*>(qb + i * TOKSTRIDE);
            #pragma unroll
            for (int r = 0; r < 4; r++) {
                const ulonglong2 kk = kt[r];      // .x = rows(4r,4r+1), .y = rows(4r+2,4r+3)
                const ulonglong2 qq = qt[r];
                kp2[i*2+0] = fma2(kk.x, S2[(2*r  )*2+0], kp2[i*2+0]);
                kp2[i*2+1] = fma2(kk.x, S2[(2*r  )*2+1], kp2[i*2+1]);
                kp2[i*2+0] = fma2(kk.y, S2[(2*r+1)*2+0], kp2[i*2+0]);
                kp2[i*2+1] = fma2(kk.y, S2[(2*r+1)*2+1], kp2[i*2+1]);
                qp2[i*2+0] = fma2(qq.x, S2[(2*r  )*2+0], qp2[i*2+0]);
                qp2[i*2+1] = fma2(qq.x, S2[(2*r  )*2+1], qp2[i*2+1]);
                qp2[i*2+0] = fma2(qq.y, S2[(2*r+1)*2+0], qp2[i*2+0]);
                qp2[i*2+1] = fma2(qq.y, S2[(2*r+1)*2+1], qp2[i*2+1]);
            }
        }
        float kp[8], qp[8];
        #pragma unroll
        for (int i = 0; i < 8; i++) { kp[i] = hadd2(kp2[i]); qp[i] = hadd2(qp2[i]); }
        // reduce across the 8 row partitions (lane bits 2,3,4)
        #pragma unroll
        for (int i = 0; i < 8; i++) {
            kp[i] += __shfl_xor_sync(~0u, kp[i], 4);
            kp[i] += __shfl_xor_sync(~0u, kp[i], 8);
            kp[i] += __shfl_xor_sync(~0u, kp[i], 16);
            qp[i] += __shfl_xor_sync(~0u, qp[i], 4);
            qp[i] += __shfl_xor_sync(~0u, qp[i], 8);
            qp[i] += __shfl_xor_sync(~0u, qp[i], 16);
        }

        // ---- scalar window recurrence, per column ----
        const float D1 = d0, D2 = D1 * d1, D3 = D2 * d2, D4 = D3 * d3;
        const float f12 = d1, f23 = d2, f34 = d3;
        const float f13 = d1 * d2, f24 = d2 * d3;
        const float f14 = f13 * d3;
        float u1[2], u2[2], u3[2], u4[2], o1[2], o2[2], o3[2], o4[2];
        float e1[2], e2[2], e3[2], e4[2];
        const float vv0[2] = {v0.x, v0.y}, vv1[2] = {v1.x, v1.y};
        const float vv2[2] = {v2.x, v2.y}, vv3[2] = {v3.x, v3.y};
        #pragma unroll
        for (int c = 0; c < 2; c++) {
            u1[c] = b0 * (vv0[c] - d0 * kp[0*2+c]);
            u2[c] = b1 * (vv1[c] - d1 * (D1 * kp[1*2+c] + A0.x * u1[c]));
            u3[c] = b2 * (vv2[c] - d2 * (D2 * kp[2*2+c] + f12 * A0.y * u1[c] + A0.z * u2[c]));
            u4[c] = b3 * (vv3[c] - d3 * (D3 * kp[3*2+c] + f13 * A0.w * u1[c]
                                         + f23 * A1.x * u2[c] + A1.y * u3[c]));
            o1[c] = (D1 * qp[0*2+c] + A1.z * u1[c]) * scale;
            o2[c] = (D2 * qp[1*2+c] + f12 * A1.w * u1[c] + A2.x * u2[c]) * scale;
            o3[c] = (D3 * qp[2*2+c] + f13 * A2.y * u1[c] + f23 * A2.z * u2[c]
                     + A2.w * u3[c]) * scale;
            o4[c] = (D4 * qp[3*2+c] + f14 * A3.x * u1[c] + f24 * A3.y * u2[c]
                     + f34 * A3.z * u3[c] + A3.w * u4[c]) * scale;
            e1[c] = f14 * u1[c]; e2[c] = f24 * u2[c]; e3[c] = f34 * u3[c]; e4[c] = u4[c];
        }

        // ---- packed rank-4 update: S = D4*S + sum_j k_j * e_j ----
        const ull D4_2 = pack2(D4, D4);
        ull e1_2[2], e2_2[2], e3_2[2], e4_2[2];
        #pragma unroll
        for (int c = 0; c < 2; c++) {
            e1_2[c] = pack2(e1[c], e1[c]); e2_2[c] = pack2(e2[c], e2[c]);
            e3_2[c] = pack2(e3[c], e3[c]); e4_2[c] = pack2(e4[c], e4[c]);
        }
        {
            const ulonglong2* t1 = reinterpret_cast<const ulonglong2*>(kb + 0 * TOKSTRIDE);
            const ulonglong2* t2 = reinterpret_cast<const ulonglong2*>(kb + 1 * TOKSTRIDE);
            const ulonglong2* t3 = reinterpret_cast<const ulonglong2*>(kb + 2 * TOKSTRIDE);
            const ulonglong2* t4 = reinterpret_cast<const ulonglong2*>(kb + 3 * TOKSTRIDE);
            #pragma unroll
            for (int r = 0; r < 4; r++) {
                const ulonglong2 k1 = t1[r], k2 = t2[r], k3 = t3[r], k4 = t4[r];
                #pragma unroll
                for (int c = 0; c < 2; c++) {
                    ull a0 = mul2(k1.x, e1_2[c]);
                    a0 = fma2(k2.x, e2_2[c], a0);
                    a0 = fma2(k3.x, e3_2[c], a0);
                    a0 = fma2(k4.x, e4_2[c], a0);
                    S2[(2*r  )*2+c] = fma2(S2[(2*r  )*2+c], D4_2, a0);
                    ull a1 = mul2(k1.y, e1_2[c]);
                    a1 = fma2(k2.y, e2_2[c], a1);
                    a1 = fma2(k3.y, e3_2[c], a1);
                    a1 = fma2(k4.y, e4_2[c], a1);
                    S2[(2*r+1)*2+c] = fma2(S2[(2*r+1)*2+c], D4_2, a1);
                }
            }
        }

        // ---- output: rp 0..3 writes token w*4+rp, both cols (float2) ----
        if (rp < 4) {
            const float ox = (rp == 0) ? o1[0] : (rp == 1) ? o2[0] : (rp == 2) ? o3[0] : o4[0];
            const float oy = (rp == 0) ? o1[1] : (rp == 1) ? o2[1] : (rp == 2) ? o3[1] : o4[1];
            *reinterpret_cast<float2*>(
                &out[((row0 + (size_t)w * 4 + rp) * HV + h) * DV + col0]) = make_float2(ox, oy);
        }
    }
}

// ---------------- launch ------------------------------------------------------
extern "C" void kernel_launch(void* const* d_in, const int* in_sizes, int n_in,
                              void* d_out, int out_size)
{
    const float* x    = (const float*)d_in[0];  // mixed_qkv [4096, 8192]
    const float* b    = (const float*)d_in[1];  // [4096, 32]
    const float* a    = (const float*)d_in[2];  // [4096, 32]
    const float* w    = (const float*)d_in[3];  // conv_weights [8192, 4]
    const float* dt   = (const float*)d_in[4];  // [32]
    const float* alog = (const float*)d_in[5];  // [32]
    // d_in[6] = cu_seqlens (equal-length; unused)

    conv_kernel<<<dim3(NTOK / TT, 64), 128>>>(x, w);
    gate_kernel<<<(NTOK * HV + 255) / 256, 256>>>(b, a, dt, alog);
    dot_kernel<<<dim3(NW / 4, HK), 128>>>();
    scan_kernel<<<128, 256>>>((float*)d_out);
}